// round 15
// baseline (speedup 1.0000x reference)
#include <cuda_runtime.h>
#include <stdint.h>

// Transducer loss: unnormalized linear-domain fp32 recurrence.
// R15: gathers held one full macro deep in registers (G[8][8]) so every LDS
// has an 8-step issue->use distance; raw rows staged 2 macros ahead, LDG 4
// macros ahead (RA/RB parity sets). Renorm numerics identical to R14.

#define INV_LN2 1.44269504088896340736f
#define LN2_F   0.69314718055994530942f

static constexpr int B  = 128;
static constexpr int T  = 2000;
static constexpr int C  = 62;
static constexpr int L  = 256;

typedef unsigned long long ull;
typedef unsigned int u32;

__device__ float g_prob[B * T * C + 32 * C];  // padded: prefetch reads to t<2032
__device__ float g_lgs[B * T];                // log2 of per-row sum
__device__ float g_bloss[B];

static __device__ __forceinline__ float ex2f(float x) {
    float y; asm("ex2.approx.ftz.f32 %0, %1;" : "=f"(y) : "f"(x)); return y;
}
static __device__ __forceinline__ float lg2f(float x) {
    float y; asm("lg2.approx.ftz.f32 %0, %1;" : "=f"(y) : "f"(x)); return y;
}
static __device__ __forceinline__ float p2f(int e) {   // 2^e, e in [-126,127]
    return __uint_as_float((u32)(127 + e) << 23);
}
static __device__ __forceinline__ ull pk(float lo, float hi) {
    ull r; asm("mov.b64 %0, {%1, %2};" : "=l"(r) : "f"(lo), "f"(hi)); return r;
}
static __device__ __forceinline__ void upk(ull v, float& lo, float& hi) {
    asm("mov.b64 {%0, %1}, %2;" : "=f"(lo), "=f"(hi) : "l"(v));
}
static __device__ __forceinline__ ull add2(ull a, ull b) {
    ull r; asm("add.rn.f32x2 %0, %1, %2;" : "=l"(r) : "l"(a), "l"(b)); return r;
}
static __device__ __forceinline__ ull mul2(ull a, ull b) {
    ull r; asm("mul.rn.f32x2 %0, %1, %2;" : "=l"(r) : "l"(a), "l"(b)); return r;
}

// ---------------------------------------------------------------------------
// K1: streaming map + fused rowsums, float4 vectorized. (At LTS cap.)
// ---------------------------------------------------------------------------
__global__ __launch_bounds__(256) void prob_kernel(const float* __restrict__ x) {
    __shared__ float sp[32 * C];
    const long base = (long)blockIdx.x * (32 * C);
    const float4* xv = (const float4*)(x + base);
    float4* pv = (float4*)(g_prob + base);

#pragma unroll
    for (int it = 0; it < 2; it++) {
        const int i = threadIdx.x + it * 256;
        if (i < (32 * C) / 4) {
            const float4 v = __ldg(xv + i);
            float4 p;
            p.x = ex2f(v.x * INV_LN2);
            p.y = ex2f(v.y * INV_LN2);
            p.z = ex2f(v.z * INV_LN2);
            p.w = ex2f(v.w * INV_LN2);
            pv[i] = p;
            *(float4*)(sp + 4 * i) = p;
        }
    }
    __syncthreads();

    const int r = threadIdx.x >> 3;
    const int k = threadIdx.x & 7;
    float s = 0.f;
    const int off = r * C + k * 8;
#pragma unroll
    for (int i = 0; i < 8; i++)
        if (k * 8 + i < C) s += sp[off + i];
    s += __shfl_xor_sync(0xffffffffu, s, 4);
    s += __shfl_xor_sync(0xffffffffu, s, 2);
    s += __shfl_xor_sync(0xffffffffu, s, 1);
    if (k == 0) g_lgs[blockIdx.x * 32 + r] = lg2f(s);
}

// ---------------------------------------------------------------------------
// K2: the recurrence. One warp per batch. State pairs (S0S1)..(S6S7) as f32x2.
// ---------------------------------------------------------------------------
__global__ __launch_bounds__(32, 1) void recur_kernel(const int* __restrict__ tg) {
    const int b = blockIdx.x;
    const int lane = threadIdx.x;

    __shared__ float sbuf[2][8][64];   // [buf][slot][padded row]

    const float* prow = g_prob + (long)b * T * C;

    // Time-invariant gather addresses.
    const float* ap[8];
    int tgt0 = 0;
#pragma unroll
    for (int j = 0; j < 8; j++) {
        const int tc = __ldg(tg + b * L + lane * 8 + j);
        if (j == 0) tgt0 = tc;
        ap[j] = &sbuf[0][0][tc];
    }

    // ---- prologue ----
    // buf0 <- macro0 rows (t=1..8); buf1 <- macro1 rows (t=9..16);
    // RA <- macro2; RB <- macro3; pr -> macro4.
    float2 RA[8], RB[8];
#pragma unroll
    for (int s = 0; s < 8; s++) {
        RA[s] = *(const float2*)(prow + (1 + s) * C + 2 * lane);
        RB[s] = *(const float2*)(prow + (9 + s) * C + 2 * lane);
    }
#pragma unroll
    for (int s = 0; s < 8; s++) {
        *(float2*)&sbuf[0][s][2 * lane] = RA[s];
        *(float2*)&sbuf[1][s][2 * lane] = RB[s];
    }
#pragma unroll
    for (int s = 0; s < 8; s++) {
        RA[s] = *(const float2*)(prow + (17 + s) * C + 2 * lane);
        RB[s] = *(const float2*)(prow + (25 + s) * C + 2 * lane);
    }
    const float2* pr = (const float2*)(prow + 33 * C + 2 * lane);
    __syncwarp();

    // ---- fused normalization-correction partial sum (off critical path) ----
    float corr = 0.f;
    {
        const float4* lgv = (const float4*)(g_lgs + b * T);
#pragma unroll 4
        for (int i = lane; i < T / 4; i += 32) {
            const float4 v = __ldg(lgv + i);
            corr += (v.x + v.y) + (v.z + v.w);
        }
    }

    // Macro-deep gather buffer: G[k][j] = prob(step k of current macro).
    float G[8][8];
#pragma unroll
    for (int k = 0; k < 8; k++)
#pragma unroll
        for (int j = 0; j < 8; j++)
            G[k][j] = ap[j][k * 64];          // buf0 = macro0

    ull v0 = 0ull, v1 = 0ull, v2 = 0ull, v3 = 0ull;
    if (lane == 0) v0 = pk(__ldg(prow + tgt0), 0.f);   // t = 0 init

    int base = 0;                              // true = S * 2^base, per lane
    float cc = (lane == 0) ? 0.f : 1.f;        // folded carry factor
    float pf1 = 1.f, pf2 = 1.f;                // pending renorm scale
    int pnb = 0;

#define STEP(K, NW)                                                            \
    do {                                                                        \
        float lo0, hi0, lo1, hi1, lo2, hi2, lo3, hi3;                           \
        upk(v0, lo0, hi0); upk(v1, lo1, hi1);                                   \
        upk(v2, lo2, hi2); upk(v3, lo3, hi3);                                   \
        const float cr = __shfl_up_sync(0xffffffffu, hi3, 1) * cc;              \
        v0 = mul2(add2(v0, pk(cr,  lo0)), pk(G[K][0], G[K][1]));                \
        v1 = mul2(add2(v1, pk(hi0, lo1)), pk(G[K][2], G[K][3]));                \
        v2 = mul2(add2(v2, pk(hi1, lo2)), pk(G[K][4], G[K][5]));                \
        v3 = mul2(add2(v3, pk(hi2, lo3)), pk(G[K][6], G[K][7]));                \
        G[K][0] = ap[0][NW]; G[K][1] = ap[1][NW];                               \
        G[K][2] = ap[2][NW]; G[K][3] = ap[3][NW];                               \
        G[K][4] = ap[4][NW]; G[K][5] = ap[5][NW];                               \
        G[K][6] = ap[6][NW]; G[K][7] = ap[7][NW];                               \
    } while (0)

#define STEP_NP(K)                                                             \
    do {                                                                        \
        float lo0, hi0, lo1, hi1, lo2, hi2, lo3, hi3;                           \
        upk(v0, lo0, hi0); upk(v1, lo1, hi1);                                   \
        upk(v2, lo2, hi2); upk(v3, lo3, hi3);                                   \
        const float cr = __shfl_up_sync(0xffffffffu, hi3, 1) * cc;              \
        v0 = mul2(add2(v0, pk(cr,  lo0)), pk(G[K][0], G[K][1]));                \
        v1 = mul2(add2(v1, pk(hi0, lo1)), pk(G[K][2], G[K][3]));                \
        v2 = mul2(add2(v2, pk(hi1, lo2)), pk(G[K][4], G[K][5]));                \
        v3 = mul2(add2(v3, pk(hi2, lo3)), pk(G[K][6], G[K][7]));                \
    } while (0)

// COMPUTE: derive pending scale/base. Pin lane max at 2^0 (e=127) — R11 exact.
#define RCOMP()                                                                 \
    do {                                                                        \
        float xa, xb; u32 m;                                                    \
        upk(v0, xa, xb); m = max(__float_as_uint(xa), __float_as_uint(xb));     \
        upk(v1, xa, xb); m = max(m, max(__float_as_uint(xa), __float_as_uint(xb))); \
        upk(v2, xa, xb); m = max(m, max(__float_as_uint(xa), __float_as_uint(xb))); \
        upk(v3, xa, xb); m = max(m, max(__float_as_uint(xa), __float_as_uint(xb))); \
        const int e = (int)(m >> 23);                                           \
        const int d = min(127, max(-126, 127 - e));                             \
        const int tb = (m == 0u) ? base : (base - d);                           \
        const int bp = __shfl_up_sync(0xffffffffu, tb, 1);                      \
        int nb = tb;                                                            \
        if (lane > 0) nb = (m == 0u) ? bp : max(tb, bp - 48);                   \
        const int sh = base - nb;                                               \
        const int s1 = min(127, max(-126, sh));                                 \
        const int s2 = min(127, max(-126, sh - s1));                            \
        pf1 = p2f(s1); pf2 = p2f(s2); pnb = nb;                                 \
    } while (0)

// APPLY: rescale state, commit base, rebuild folded carry factor.
#define RAPPLY()                                                                \
    do {                                                                        \
        const ull z1 = pk(pf1, pf1), z2 = pk(pf2, pf2);                         \
        v0 = mul2(mul2(v0, z1), z2); v1 = mul2(mul2(v1, z1), z2);               \
        v2 = mul2(mul2(v2, z1), z2); v3 = mul2(mul2(v3, z1), z2);               \
        base = pnb;                                                             \
        const int bpf = __shfl_up_sync(0xffffffffu, base, 1);                   \
        const int diff = bpf - base;       /* <= +48 by clamp invariant */      \
        int d1 = diff >> 1;                                                     \
        int d2 = diff - d1;                                                     \
        d1 = min(126, max(-126, d1)); d2 = min(126, max(-126, d2));             \
        cc = (lane == 0) ? 0.f : p2f(d1) * p2f(d2);                             \
    } while (0)

// Macro m (parity P): STS buf[P] <- RS (macro m+2 rows), LDG RS <- macro m+4,
// 8 steps; each step refills G[k] from buf[1-P] (macro m+1) at slot k.
// Renorm cadence 4: RCOMP after steps 2,6; RAPPLY after steps 4,8.
#define MACRO(P, RS)                                                            \
    do {                                                                        \
        _Pragma("unroll")                                                       \
        for (int s = 0; s < 8; s++)                                             \
            *(float2*)&sbuf[P][s][2 * lane] = RS[s];                            \
        _Pragma("unroll")                                                       \
        for (int s = 0; s < 8; s++) RS[s] = __ldg(pr + s * 31);                 \
        pr += 248;                                                              \
        __syncwarp();                                                           \
        STEP(0, ((1 - (P)) * 8 + 0) * 64);                                      \
        STEP(1, ((1 - (P)) * 8 + 1) * 64);  RCOMP();                            \
        STEP(2, ((1 - (P)) * 8 + 2) * 64);                                      \
        STEP(3, ((1 - (P)) * 8 + 3) * 64);  RAPPLY();                           \
        STEP(4, ((1 - (P)) * 8 + 4) * 64);                                      \
        STEP(5, ((1 - (P)) * 8 + 5) * 64);  RCOMP();                            \
        STEP(6, ((1 - (P)) * 8 + 6) * 64);                                      \
        STEP(7, ((1 - (P)) * 8 + 7) * 64);  RAPPLY();                           \
    } while (0)

    // Macros m = 0..248 cover t = 1..1992.
    for (int mm = 0; mm < 124; mm++) { MACRO(0, RA); MACRO(1, RB); }
    MACRO(0, RA);   // m = 248; its refills gathered macro 249 (t=1993..2000)

    // Tail: t = 1993..1999 (7 steps), G already gathered.
    STEP_NP(0);
    STEP_NP(1);  RCOMP();
    STEP_NP(2);
    STEP_NP(3);  RAPPLY();
    STEP_NP(4);
    STEP_NP(5);
    STEP_NP(6);

    // reduce correction across lanes (deterministic tree)
#pragma unroll
    for (int o = 16; o; o >>= 1) corr += __shfl_xor_sync(0xffffffffu, corr, o);

    if (lane == 31) {
        float s7lo, s7hi; upk(v3, s7lo, s7hi);
        const float alpha2 = lg2f(s7hi) + (float)base;     // raw log2 alpha
        g_bloss[b] = (corr - alpha2) * LN2_F;              // normalize, nats
    }
#undef STEP
#undef STEP_NP
#undef RCOMP
#undef RAPPLY
#undef MACRO
}

// ---------------------------------------------------------------------------
// K3: deterministic mean over the batch.
// ---------------------------------------------------------------------------
__global__ __launch_bounds__(128) void reduce_kernel(float* __restrict__ out) {
    const int i = threadIdx.x;
    float v = g_bloss[i];
#pragma unroll
    for (int o = 16; o; o >>= 1) v += __shfl_xor_sync(0xffffffffu, v, o);
    __shared__ float ws[4];
    if ((i & 31) == 0) ws[i >> 5] = v;
    __syncthreads();
    if (i == 0) out[0] = (ws[0] + ws[1] + ws[2] + ws[3]) * (1.0f / (float)B);
}

// ---------------------------------------------------------------------------
extern "C" void kernel_launch(void* const* d_in, const int* in_sizes, int n_in,
                              void* d_out, int out_size) {
    const float* x = (const float*)d_in[0];   // [B, T, C] float32
    const int* tg = (const int*)d_in[1];      // [B, L] int32
    float* out = (float*)d_out;

    (void)in_sizes; (void)n_in; (void)out_size;

    prob_kernel<<<(B * T) / 32, 256>>>(x);
    recur_kernel<<<B, 32>>>(tg);
    reduce_kernel<<<1, 128>>>(out);
}

// round 16
// speedup vs baseline: 1.0216x; 1.0216x over previous
#include <cuda_runtime.h>
#include <stdint.h>

// Transducer loss: unnormalized linear-domain fp32 recurrence.
// R16: R14 numerics (cadence 4, pin 2^0, -48 clamp, adoption) with
//  - even-odd state packing (odd update needs no shifted operand)
//  - time-paired smem staging -> 4x LDS.64 gathers per step (4-buf ring)
//  - single-stage renorm scales with exact zero-flush.

#define INV_LN2 1.44269504088896340736f
#define LN2_F   0.69314718055994530942f

static constexpr int B  = 128;
static constexpr int T  = 2000;
static constexpr int C  = 62;
static constexpr int L  = 256;

typedef unsigned long long ull;
typedef unsigned int u32;

__device__ float g_prob[B * T * C + 32 * C];  // padded: reads to t<2032
__device__ float g_lgs[B * T];
__device__ float g_bloss[B];

static __device__ __forceinline__ float ex2f(float x) {
    float y; asm("ex2.approx.ftz.f32 %0, %1;" : "=f"(y) : "f"(x)); return y;
}
static __device__ __forceinline__ float lg2f(float x) {
    float y; asm("lg2.approx.ftz.f32 %0, %1;" : "=f"(y) : "f"(x)); return y;
}
static __device__ __forceinline__ float p2f(int e) {   // 2^e, e in [-126,127]
    return __uint_as_float((u32)(127 + e) << 23);
}
static __device__ __forceinline__ ull pk(float lo, float hi) {
    ull r; asm("mov.b64 %0, {%1, %2};" : "=l"(r) : "f"(lo), "f"(hi)); return r;
}
static __device__ __forceinline__ void upk(ull v, float& lo, float& hi) {
    asm("mov.b64 {%0, %1}, %2;" : "=f"(lo), "=f"(hi) : "l"(v));
}
static __device__ __forceinline__ ull add2(ull a, ull b) {
    ull r; asm("add.rn.f32x2 %0, %1, %2;" : "=l"(r) : "l"(a), "l"(b)); return r;
}
static __device__ __forceinline__ ull mul2(ull a, ull b) {
    ull r; asm("mul.rn.f32x2 %0, %1, %2;" : "=l"(r) : "l"(a), "l"(b)); return r;
}

// ---------------------------------------------------------------------------
// K1: streaming map + fused rowsums, float4 vectorized. (At LTS cap.)
// ---------------------------------------------------------------------------
__global__ __launch_bounds__(256) void prob_kernel(const float* __restrict__ x) {
    __shared__ float sp[32 * C];
    const long base = (long)blockIdx.x * (32 * C);
    const float4* xv = (const float4*)(x + base);
    float4* pv = (float4*)(g_prob + base);

#pragma unroll
    for (int it = 0; it < 2; it++) {
        const int i = threadIdx.x + it * 256;
        if (i < (32 * C) / 4) {
            const float4 v = __ldg(xv + i);
            float4 p;
            p.x = ex2f(v.x * INV_LN2);
            p.y = ex2f(v.y * INV_LN2);
            p.z = ex2f(v.z * INV_LN2);
            p.w = ex2f(v.w * INV_LN2);
            pv[i] = p;
            *(float4*)(sp + 4 * i) = p;
        }
    }
    __syncthreads();

    const int r = threadIdx.x >> 3;
    const int k = threadIdx.x & 7;
    float s = 0.f;
    const int off = r * C + k * 8;
#pragma unroll
    for (int i = 0; i < 8; i++)
        if (k * 8 + i < C) s += sp[off + i];
    s += __shfl_xor_sync(0xffffffffu, s, 4);
    s += __shfl_xor_sync(0xffffffffu, s, 2);
    s += __shfl_xor_sync(0xffffffffu, s, 1);
    if (k == 0) g_lgs[blockIdx.x * 32 + r] = lg2f(s);
}

// ---------------------------------------------------------------------------
// K2: the recurrence. One warp per batch.
// State: Ea=(S0,S2) Eb=(S4,S6) Oa=(S1,S3) Ob=(S5,S7); labels 8*lane+j.
// Smem: 4-buffer ring, rows pair-interleaved: slot (buf,p2) holds times
// (8m+2p2+1, 8m+2p2+2) as float2 per column.
// ---------------------------------------------------------------------------
__global__ __launch_bounds__(32, 1) void recur_kernel(const int* __restrict__ tg) {
    const int b = blockIdx.x;
    const int lane = threadIdx.x;

    __shared__ float sbuf[4][4][128];   // [buf][pair][col*2 + k]

    const float* prow = g_prob + (long)b * T * C;

    // Time-invariant gather bases (float2 per (col, time-pair)).
    const float* ap2[8];
    int tgt0 = 0;
#pragma unroll
    for (int j = 0; j < 8; j++) {
        const int tc = __ldg(tg + b * L + lane * 8 + j);
        if (j == 0) tgt0 = tc;
        ap2[j] = &sbuf[0][0][tc * 2];
    }

    // ---- prologue ----
    float2 RA[8], RB[8];
#pragma unroll
    for (int s = 0; s < 8; s++) {
        RA[s] = *(const float2*)(prow + (1 + s) * C + 2 * lane);   // macro0
        RB[s] = *(const float2*)(prow + (9 + s) * C + 2 * lane);   // macro1
    }
    // stage macro0 -> buf0, macro1 -> buf1 (pair-interleaved)
#pragma unroll
    for (int s2 = 0; s2 < 4; s2++) {
        *(float2*)&sbuf[0][s2][4 * lane]     = make_float2(RA[2 * s2].x, RA[2 * s2 + 1].x);
        *(float2*)&sbuf[0][s2][4 * lane + 2] = make_float2(RA[2 * s2].y, RA[2 * s2 + 1].y);
        *(float2*)&sbuf[1][s2][4 * lane]     = make_float2(RB[2 * s2].x, RB[2 * s2 + 1].x);
        *(float2*)&sbuf[1][s2][4 * lane + 2] = make_float2(RB[2 * s2].y, RB[2 * s2 + 1].y);
    }
#pragma unroll
    for (int s = 0; s < 8; s++) {
        RA[s] = *(const float2*)(prow + (17 + s) * C + 2 * lane);  // macro2
        RB[s] = *(const float2*)(prow + (25 + s) * C + 2 * lane);  // macro3
    }
    const float2* pr = (const float2*)(prow + 33 * C + 2 * lane);  // macro4
    __syncwarp();

    // ---- fused normalization-correction partial sum ----
    float corr = 0.f;
    {
        const float4* lgv = (const float4*)(g_lgs + b * T);
#pragma unroll 4
        for (int i = lane; i < T / 4; i += 32) {
            const float4 v = __ldg(lgv + i);
            corr += (v.x + v.y) + (v.z + v.w);
        }
    }

    // Gather ping-pong: g2X[j] = (prob(t_even), prob(t_odd)) for label j.
    float2 g2A[8], g2B[8];
#pragma unroll
    for (int j = 0; j < 8; j++)
        g2A[j] = *(const float2*)(ap2[j] + 0);      // buf0 pair0 (t=1,2)

    ull Ea = 0ull, Eb = 0ull, Oa = 0ull, Ob = 0ull;
    if (lane == 0) Ea = pk(__ldg(prow + tgt0), 0.f);   // t=0: S0 only

    int base = 0;
    float cc = (lane == 0) ? 0.f : 1.f;
    float pf = 1.f;
    int pnb = 0;

// One step using field F (x = even, y = odd) of gather set GS; optionally
// refill set GO from smem at float-offset OFF.
#define STEPF(GS, F, GO, OFF, DOLOAD)                                          \
    do {                                                                        \
        float s1, s3, s5, s7;                                                   \
        upk(Oa, s1, s3); upk(Ob, s5, s7);                                       \
        const float cr = __shfl_up_sync(0xffffffffu, s7, 1) * cc;               \
        Oa = mul2(add2(Oa, Ea), pk(GS[1].F, GS[3].F));                          \
        Ob = mul2(add2(Ob, Eb), pk(GS[5].F, GS[7].F));                          \
        Ea = mul2(add2(Ea, pk(cr, s1)), pk(GS[0].F, GS[2].F));                  \
        Eb = mul2(add2(Eb, pk(s3, s5)), pk(GS[4].F, GS[6].F));                  \
        if (DOLOAD) {                                                           \
            GO[0] = *(const float2*)(ap2[0] + (OFF));                           \
            GO[1] = *(const float2*)(ap2[1] + (OFF));                           \
            GO[2] = *(const float2*)(ap2[2] + (OFF));                           \
            GO[3] = *(const float2*)(ap2[3] + (OFF));                           \
            GO[4] = *(const float2*)(ap2[4] + (OFF));                           \
            GO[5] = *(const float2*)(ap2[5] + (OFF));                           \
            GO[6] = *(const float2*)(ap2[6] + (OFF));                           \
            GO[7] = *(const float2*)(ap2[7] + (OFF));                           \
        }                                                                       \
    } while (0)

// COMPUTE: pin lane max at 2^0, -48 clamp, adoption (R14 numerics).
#define RCOMP()                                                                 \
    do {                                                                        \
        float xa, xb; u32 m;                                                    \
        upk(Ea, xa, xb); m = max(__float_as_uint(xa), __float_as_uint(xb));     \
        upk(Eb, xa, xb); m = max(m, max(__float_as_uint(xa), __float_as_uint(xb))); \
        upk(Oa, xa, xb); m = max(m, max(__float_as_uint(xa), __float_as_uint(xb))); \
        upk(Ob, xa, xb); m = max(m, max(__float_as_uint(xa), __float_as_uint(xb))); \
        const int e = (int)(m >> 23);                                           \
        const int d = min(127, max(-126, 127 - e));                             \
        const int tb = (m == 0u) ? base : (base - d);                           \
        const int bp = __shfl_up_sync(0xffffffffu, tb, 1);                      \
        int nb = tb;                                                            \
        if (lane > 0) nb = (m == 0u) ? bp : max(tb, bp - 48);                   \
        const int sh = base - nb;                                               \
        pf = (sh < -126) ? 0.f : p2f(min(127, sh));                             \
        pnb = nb;                                                               \
    } while (0)

// APPLY: single exact pow2 rescale (sub-2^-126 -> exact 0 flush).
#define RAPPLY()                                                                \
    do {                                                                        \
        const ull z = pk(pf, pf);                                               \
        Ea = mul2(Ea, z); Eb = mul2(Eb, z);                                     \
        Oa = mul2(Oa, z); Ob = mul2(Ob, z);                                     \
        base = pnb;                                                             \
        const int bpf = __shfl_up_sync(0xffffffffu, base, 1);                   \
        const int diff = bpf - base;       /* <= +48 by clamp invariant */      \
        cc = (lane == 0 || diff < -126) ? 0.f : p2f(min(126, diff));            \
    } while (0)

#define GOFF(TB, P2) (((TB) * 4 + (P2)) * 128)

// Macro m: P4 = m&3 (consume buf P4), stage RS (macro m+2) into buf (P4+2)&3,
// LDG RS <- macro m+4. 8 steps (4 pairs), renorm cadence 4.
// Pair parity within macro: pairs 0,2 consume g2A; 1,3 consume g2B.
#define MACRO(P4, RS)                                                           \
    do {                                                                        \
        _Pragma("unroll")                                                       \
        for (int s2 = 0; s2 < 4; s2++) {                                        \
            *(float2*)&sbuf[((P4) + 2) & 3][s2][4 * lane] =                     \
                make_float2(RS[2 * s2].x, RS[2 * s2 + 1].x);                    \
            *(float2*)&sbuf[((P4) + 2) & 3][s2][4 * lane + 2] =                 \
                make_float2(RS[2 * s2].y, RS[2 * s2 + 1].y);                    \
        }                                                                       \
        _Pragma("unroll")                                                       \
        for (int s = 0; s < 8; s++) RS[s] = __ldg(pr + s * 31);                 \
        pr += 248;                                                              \
        __syncwarp();                                                           \
        STEPF(g2A, x, g2B, GOFF(P4, 1), 1);                                     \
        STEPF(g2A, y, g2B, 0, 0);              RCOMP();                         \
        STEPF(g2B, x, g2A, GOFF(P4, 2), 1);                                     \
        STEPF(g2B, y, g2A, 0, 0);              RAPPLY();                        \
        STEPF(g2A, x, g2B, GOFF(P4, 3), 1);                                     \
        STEPF(g2A, y, g2B, 0, 0);              RCOMP();                         \
        STEPF(g2B, x, g2A, GOFF(((P4) + 1) & 3, 0), 1);                         \
        STEPF(g2B, y, g2A, 0, 0);              RAPPLY();                        \
    } while (0)

    // Macros m = 0..248 cover t = 1..1992.
    for (int mm = 0; mm < 62; mm++) {
        MACRO(0, RA); MACRO(1, RB); MACRO(2, RA); MACRO(3, RB);
    }
    MACRO(0, RA);   // m = 248 (stages padded macro 250; LDG padded macro 252)

    // Tail: t = 1993..1999 (7 steps) from buf1 (macro 249, staged at m=247).
    STEPF(g2A, x, g2B, GOFF(1, 1), 1);          // t=1993
    STEPF(g2A, y, g2B, 0, 0);   RCOMP();        // t=1994
    STEPF(g2B, x, g2A, GOFF(1, 2), 1);          // t=1995
    STEPF(g2B, y, g2A, 0, 0);   RAPPLY();       // t=1996
    STEPF(g2A, x, g2B, GOFF(1, 3), 1);          // t=1997
    STEPF(g2A, y, g2B, 0, 0);                   // t=1998
    STEPF(g2B, x, g2A, 0, 0);                   // t=1999

    // reduce correction across lanes (deterministic tree)
#pragma unroll
    for (int o = 16; o; o >>= 1) corr += __shfl_xor_sync(0xffffffffu, corr, o);

    if (lane == 31) {
        float s5, s7; upk(Ob, s5, s7);
        const float alpha2 = lg2f(s7) + (float)base;       // raw log2 alpha
        g_bloss[b] = (corr - alpha2) * LN2_F;              // normalize, nats
    }
#undef STEPF
#undef RCOMP
#undef RAPPLY
#undef GOFF
#undef MACRO
}

// ---------------------------------------------------------------------------
// K3: deterministic mean over the batch.
// ---------------------------------------------------------------------------
__global__ __launch_bounds__(128) void reduce_kernel(float* __restrict__ out) {
    const int i = threadIdx.x;
    float v = g_bloss[i];
#pragma unroll
    for (int o = 16; o; o >>= 1) v += __shfl_xor_sync(0xffffffffu, v, o);
    __shared__ float ws[4];
    if ((i & 31) == 0) ws[i >> 5] = v;
    __syncthreads();
    if (i == 0) out[0] = (ws[0] + ws[1] + ws[2] + ws[3]) * (1.0f / (float)B);
}

// ---------------------------------------------------------------------------
extern "C" void kernel_launch(void* const* d_in, const int* in_sizes, int n_in,
                              void* d_out, int out_size) {
    const float* x = (const float*)d_in[0];   // [B, T, C] float32
    const int* tg = (const int*)d_in[1];      // [B, L] int32
    float* out = (float*)d_out;

    (void)in_sizes; (void)n_in; (void)out_size;

    prob_kernel<<<(B * T) / 32, 256>>>(x);
    recur_kernel<<<B, 32>>>(tg);
    reduce_kernel<<<1, 128>>>(out);
}

// round 17
// speedup vs baseline: 1.0409x; 1.0189x over previous
#include <cuda_runtime.h>
#include <stdint.h>

// Transducer loss: unnormalized linear-domain fp32 recurrence.
// R17: fused 2-step recurrence S_{t+2} = A*S + B*S<1> + C*S<2> (A=p*q, C=p<1>*q,
// B=A+C). Halves per-step shfl-chain/renorm/loop overhead. R14 staging (2-buf,
// 16-row macros); renorm cadence 4 single-steps, pin 2^0, -48 clamp, adoption.

#define INV_LN2 1.44269504088896340736f
#define LN2_F   0.69314718055994530942f

static constexpr int B  = 128;
static constexpr int T  = 2000;
static constexpr int C  = 62;
static constexpr int L  = 256;

typedef unsigned long long ull;
typedef unsigned int u32;

__device__ float g_prob[B * T * C + 32 * C];  // padded: reads to row < 2032
__device__ float g_lgs[B * T];
__device__ float g_bloss[B];

static __device__ __forceinline__ float ex2f(float x) {
    float y; asm("ex2.approx.ftz.f32 %0, %1;" : "=f"(y) : "f"(x)); return y;
}
static __device__ __forceinline__ float lg2f(float x) {
    float y; asm("lg2.approx.ftz.f32 %0, %1;" : "=f"(y) : "f"(x)); return y;
}
static __device__ __forceinline__ float p2f(int e) {   // 2^e, e in [-126,127]
    return __uint_as_float((u32)(127 + e) << 23);
}
static __device__ __forceinline__ ull pk(float lo, float hi) {
    ull r; asm("mov.b64 %0, {%1, %2};" : "=l"(r) : "f"(lo), "f"(hi)); return r;
}
static __device__ __forceinline__ void upk(ull v, float& lo, float& hi) {
    asm("mov.b64 {%0, %1}, %2;" : "=f"(lo), "=f"(hi) : "l"(v));
}
static __device__ __forceinline__ ull add2(ull a, ull b) {
    ull r; asm("add.rn.f32x2 %0, %1, %2;" : "=l"(r) : "l"(a), "l"(b)); return r;
}
static __device__ __forceinline__ ull mul2(ull a, ull b) {
    ull r; asm("mul.rn.f32x2 %0, %1, %2;" : "=l"(r) : "l"(a), "l"(b)); return r;
}
static __device__ __forceinline__ ull fma2(ull a, ull b, ull c) {
    ull r; asm("fma.rn.f32x2 %0, %1, %2, %3;" : "=l"(r) : "l"(a), "l"(b), "l"(c)); return r;
}

// ---------------------------------------------------------------------------
// K1: streaming map + fused rowsums, float4 vectorized. (At LTS cap.)
// ---------------------------------------------------------------------------
__global__ __launch_bounds__(256) void prob_kernel(const float* __restrict__ x) {
    __shared__ float sp[32 * C];
    const long base = (long)blockIdx.x * (32 * C);
    const float4* xv = (const float4*)(x + base);
    float4* pv = (float4*)(g_prob + base);

#pragma unroll
    for (int it = 0; it < 2; it++) {
        const int i = threadIdx.x + it * 256;
        if (i < (32 * C) / 4) {
            const float4 v = __ldg(xv + i);
            float4 p;
            p.x = ex2f(v.x * INV_LN2);
            p.y = ex2f(v.y * INV_LN2);
            p.z = ex2f(v.z * INV_LN2);
            p.w = ex2f(v.w * INV_LN2);
            pv[i] = p;
            *(float4*)(sp + 4 * i) = p;
        }
    }
    __syncthreads();

    const int r = threadIdx.x >> 3;
    const int k = threadIdx.x & 7;
    float s = 0.f;
    const int off = r * C + k * 8;
#pragma unroll
    for (int i = 0; i < 8; i++)
        if (k * 8 + i < C) s += sp[off + i];
    s += __shfl_xor_sync(0xffffffffu, s, 4);
    s += __shfl_xor_sync(0xffffffffu, s, 2);
    s += __shfl_xor_sync(0xffffffffu, s, 1);
    if (k == 0) g_lgs[blockIdx.x * 32 + r] = lg2f(s);
}

// ---------------------------------------------------------------------------
// K2: the recurrence. One warp per batch. State pairs v0=(S0,S1)..v3=(S6,S7).
// Fused steps: f covers times t = 2f+2, 2f+3 (t=0 init + t=1 scalar step).
// Macro = 16 rows = 8 fused steps. Macro m rows: 16m+2 .. 16m+17.
// ---------------------------------------------------------------------------
__global__ __launch_bounds__(32, 1) void recur_kernel(const int* __restrict__ tg) {
    const int b = blockIdx.x;
    const int lane = threadIdx.x;

    __shared__ float sbuf[2][16][64];   // [buf][slot][padded row]

    const float* prow = g_prob + (long)b * T * C;

    // Targets + time-invariant gather bases.
    int tcs[8];
    const float* ap[8];
#pragma unroll
    for (int j = 0; j < 8; j++) {
        tcs[j] = __ldg(tg + b * L + lane * 8 + j);
        ap[j] = &sbuf[0][0][tcs[j]];
    }

    // ---- prologue staging: buf0 <- macro0 (rows 2..17); R <- macro1 (18..33)
    float2 R[16];
#pragma unroll
    for (int s = 0; s < 16; s++)
        R[s] = *(const float2*)(prow + (2 + s) * C + 2 * lane);
#pragma unroll
    for (int s = 0; s < 16; s++)
        *(float2*)&sbuf[0][s][2 * lane] = R[s];
#pragma unroll
    for (int s = 0; s < 16; s++)
        R[s] = *(const float2*)(prow + (18 + s) * C + 2 * lane);
    const float2* pr = (const float2*)(prow + 34 * C + 2 * lane);
    __syncwarp();

    // ---- fused normalization-correction partial sum ----
    float corr = 0.f;
    {
        const float4* lgv = (const float4*)(g_lgs + b * T);
#pragma unroll 4
        for (int i = lane; i < T / 4; i += 32) {
            const float4 v = __ldg(lgv + i);
            corr += (v.x + v.y) + (v.z + v.w);
        }
    }

    // ---- t=0 init and t=1 scalar step ----
    float S[8] = {0.f, 0.f, 0.f, 0.f, 0.f, 0.f, 0.f, 0.f};
    if (lane == 0) S[0] = __ldg(prow + tcs[0]);
    {
        float q[8];
#pragma unroll
        for (int j = 0; j < 8; j++) q[j] = __ldg(prow + C + tcs[j]);
        const float s7p = __shfl_up_sync(0xffffffffu, S[7], 1);
        const float cr = (lane == 0) ? 0.f : s7p;
#pragma unroll
        for (int j = 7; j >= 1; j--) S[j] = (S[j] + S[j - 1]) * q[j];
        S[0] = (S[0] + cr) * q[0];
    }
    ull v0 = pk(S[0], S[1]), v1 = pk(S[2], S[3]);
    ull v2 = pk(S[4], S[5]), v3 = pk(S[6], S[7]);

    // Gather ping-pong sets (p = row 2f+2, q = row 2f+3).
    float GPa[8], GQa[8], GPb[8], GQb[8];
#pragma unroll
    for (int j = 0; j < 8; j++) { GPa[j] = ap[j][0]; GQa[j] = ap[j][64]; }

    int base = 0;
    float cc = (lane == 0) ? 0.f : 1.f;
    float pf = 1.f;
    int pnb = 0;

#define GOFF(BUF, SLOT) (((BUF) * 16 + (SLOT)) * 64)

// Fused step: consume GP/GQ, prefetch HP/HQ from slots at OFF, OFF+64.
#define STEP2(GP, GQ, HP, HQ, OFF, DOLOAD)                                     \
    do {                                                                        \
        float s0, s1, s2, s3, s4, s5, s6, s7;                                   \
        upk(v0, s0, s1); upk(v1, s2, s3);                                       \
        upk(v2, s4, s5); upk(v3, s6, s7);                                       \
        const float s7n = __shfl_up_sync(0xffffffffu, s7, 1);                   \
        const float s6n = __shfl_up_sync(0xffffffffu, s6, 1);                   \
        const float p7n = __shfl_up_sync(0xffffffffu, GP[7], 1);                \
        const float cr7 = s7n * cc;                                             \
        const float cr6 = s6n * cc;                                             \
        const ull A0 = pk(GP[0] * GQ[0], GP[1] * GQ[1]);                        \
        const ull C0 = pk(p7n   * GQ[0], GP[0] * GQ[1]);                        \
        const ull A1 = pk(GP[2] * GQ[2], GP[3] * GQ[3]);                        \
        const ull C1 = pk(GP[1] * GQ[2], GP[2] * GQ[3]);                        \
        const ull A2 = pk(GP[4] * GQ[4], GP[5] * GQ[5]);                        \
        const ull C2 = pk(GP[3] * GQ[4], GP[4] * GQ[5]);                        \
        const ull A3 = pk(GP[6] * GQ[6], GP[7] * GQ[7]);                        \
        const ull C3 = pk(GP[5] * GQ[6], GP[6] * GQ[7]);                        \
        const ull B0 = add2(A0, C0), B1 = add2(A1, C1);                         \
        const ull B2 = add2(A2, C2), B3 = add2(A3, C3);                         \
        const ull Sl0 = pk(cr7, s0), Sl1 = pk(s1, s2);                          \
        const ull Sl2 = pk(s3, s4), Sl3 = pk(s5, s6);                           \
        const ull Sll0 = pk(cr6, cr7);                                          \
        const ull ov0 = v0, ov1 = v1, ov2 = v2;                                 \
        v0 = fma2(A0, v0, fma2(B0, Sl0, mul2(C0, Sll0)));                       \
        v1 = fma2(A1, v1, fma2(B1, Sl1, mul2(C1, ov0)));                        \
        v2 = fma2(A2, v2, fma2(B2, Sl2, mul2(C2, ov1)));                        \
        v3 = fma2(A3, v3, fma2(B3, Sl3, mul2(C3, ov2)));                        \
        if (DOLOAD) {                                                           \
            HP[0] = ap[0][OFF]; HQ[0] = ap[0][(OFF) + 64];                      \
            HP[1] = ap[1][OFF]; HQ[1] = ap[1][(OFF) + 64];                      \
            HP[2] = ap[2][OFF]; HQ[2] = ap[2][(OFF) + 64];                      \
            HP[3] = ap[3][OFF]; HQ[3] = ap[3][(OFF) + 64];                      \
            HP[4] = ap[4][OFF]; HQ[4] = ap[4][(OFF) + 64];                      \
            HP[5] = ap[5][OFF]; HQ[5] = ap[5][(OFF) + 64];                      \
            HP[6] = ap[6][OFF]; HQ[6] = ap[6][(OFF) + 64];                      \
            HP[7] = ap[7][OFF]; HQ[7] = ap[7][(OFF) + 64];                      \
        }                                                                       \
    } while (0)

// COMPUTE: pin lane max at 2^0, -48 clamp, adoption (R14/R16 numerics).
#define RCOMP()                                                                 \
    do {                                                                        \
        float xa, xb; u32 m;                                                    \
        upk(v0, xa, xb); m = max(__float_as_uint(xa), __float_as_uint(xb));     \
        upk(v1, xa, xb); m = max(m, max(__float_as_uint(xa), __float_as_uint(xb))); \
        upk(v2, xa, xb); m = max(m, max(__float_as_uint(xa), __float_as_uint(xb))); \
        upk(v3, xa, xb); m = max(m, max(__float_as_uint(xa), __float_as_uint(xb))); \
        const int e = (int)(m >> 23);                                           \
        const int d = min(127, max(-126, 127 - e));                             \
        const int tb = (m == 0u) ? base : (base - d);                           \
        const int bp = __shfl_up_sync(0xffffffffu, tb, 1);                      \
        int nb = tb;                                                            \
        if (lane > 0) nb = (m == 0u) ? bp : max(tb, bp - 48);                   \
        const int sh = base - nb;                                               \
        pf = (sh < -126) ? 0.f : p2f(min(127, sh));                             \
        pnb = nb;                                                               \
    } while (0)

// APPLY: exact pow2 rescale (sub-2^-126 -> exact 0 flush).
#define RAPPLY()                                                                \
    do {                                                                        \
        const ull z = pk(pf, pf);                                               \
        v0 = mul2(v0, z); v1 = mul2(v1, z);                                     \
        v2 = mul2(v2, z); v3 = mul2(v3, z);                                     \
        base = pnb;                                                             \
        const int bpf = __shfl_up_sync(0xffffffffu, base, 1);                   \
        const int diff = bpf - base;       /* <= +48 by clamp invariant */      \
        cc = (lane == 0 || diff < -126) ? 0.f : p2f(min(126, diff));            \
    } while (0)

// Macro (mbuf): STS buf[1-mbuf] <- R (next macro rows), LDG R <- macro m+2,
// 8 fused steps consuming buf[mbuf] slots 0..15; renorm every 2 fused steps.
#define MACRO(mbuf)                                                             \
    do {                                                                        \
        _Pragma("unroll")                                                       \
        for (int s = 0; s < 16; s++)                                            \
            *(float2*)&sbuf[1 - (mbuf)][s][2 * lane] = R[s];                    \
        _Pragma("unroll")                                                       \
        for (int s = 0; s < 16; s++) R[s] = __ldg(pr + s * 31);                 \
        pr += 16 * 31;                                                          \
        __syncwarp();                                                           \
        STEP2(GPa, GQa, GPb, GQb, GOFF(mbuf, 2), 1);   RCOMP();                 \
        STEP2(GPb, GQb, GPa, GQa, GOFF(mbuf, 4), 1);   RAPPLY();                \
        STEP2(GPa, GQa, GPb, GQb, GOFF(mbuf, 6), 1);   RCOMP();                 \
        STEP2(GPb, GQb, GPa, GQa, GOFF(mbuf, 8), 1);   RAPPLY();                \
        STEP2(GPa, GQa, GPb, GQb, GOFF(mbuf, 10), 1);  RCOMP();                 \
        STEP2(GPb, GQb, GPa, GQa, GOFF(mbuf, 12), 1);  RAPPLY();                \
        STEP2(GPa, GQa, GPb, GQb, GOFF(mbuf, 14), 1);  RCOMP();                 \
        STEP2(GPb, GQb, GPa, GQa, GOFF(1 - (mbuf), 0), 1); RAPPLY();            \
    } while (0)

    // Macros m = 0..123 cover fused f = 0..991 (t = 2..1985).
    for (int mm = 0; mm < 62; mm++) { MACRO(0); MACRO(1); }

    // Tail: fused f = 992..998 (t = 1986..1999) from buf0 (staged at m=123).
    STEP2(GPa, GQa, GPb, GQb, GOFF(0, 2), 1);   RCOMP();    // t=1986,1987
    STEP2(GPb, GQb, GPa, GQa, GOFF(0, 4), 1);   RAPPLY();   // t=1988,1989
    STEP2(GPa, GQa, GPb, GQb, GOFF(0, 6), 1);   RCOMP();    // t=1990,1991
    STEP2(GPb, GQb, GPa, GQa, GOFF(0, 8), 1);   RAPPLY();   // t=1992,1993
    STEP2(GPa, GQa, GPb, GQb, GOFF(0, 10), 1);              // t=1994,1995
    STEP2(GPb, GQb, GPa, GQa, GOFF(0, 12), 1);              // t=1996,1997
    STEP2(GPa, GQa, GPb, GQb, 0, 0);                        // t=1998,1999

    // reduce correction across lanes (deterministic tree)
#pragma unroll
    for (int o = 16; o; o >>= 1) corr += __shfl_xor_sync(0xffffffffu, corr, o);

    if (lane == 31) {
        float s6f, s7f; upk(v3, s6f, s7f);
        const float alpha2 = lg2f(s7f) + (float)base;      // raw log2 alpha
        g_bloss[b] = (corr - alpha2) * LN2_F;              // normalize, nats
    }
#undef GOFF
#undef STEP2
#undef RCOMP
#undef RAPPLY
#undef MACRO
}

// ---------------------------------------------------------------------------
// K3: deterministic mean over the batch.
// ---------------------------------------------------------------------------
__global__ __launch_bounds__(128) void reduce_kernel(float* __restrict__ out) {
    const int i = threadIdx.x;
    float v = g_bloss[i];
#pragma unroll
    for (int o = 16; o; o >>= 1) v += __shfl_xor_sync(0xffffffffu, v, o);
    __shared__ float ws[4];
    if ((i & 31) == 0) ws[i >> 5] = v;
    __syncthreads();
    if (i == 0) out[0] = (ws[0] + ws[1] + ws[2] + ws[3]) * (1.0f / (float)B);
}

// ---------------------------------------------------------------------------
extern "C" void kernel_launch(void* const* d_in, const int* in_sizes, int n_in,
                              void* d_out, int out_size) {
    const float* x = (const float*)d_in[0];   // [B, T, C] float32
    const int* tg = (const int*)d_in[1];      // [B, L] int32
    float* out = (float*)d_out;

    (void)in_sizes; (void)n_in; (void)out_size;

    prob_kernel<<<(B * T) / 32, 256>>>(x);
    recur_kernel<<<B, 32>>>(tg);
    reduce_kernel<<<1, 128>>>(out);
}